// round 5
// baseline (speedup 1.0000x reference)
#include <cuda_runtime.h>

#define NB    32
#define NPTS  16384
#define SGRID 768
#define GOUT  256
#define OUT_HALF ((size_t)NB * GOUT * GOUT * 3)   // 6,291,456 floats

// Scratch (no allocations allowed): packed gl per point + per-batch key minima.
__device__ int g_gl[NB * NPTS];
__device__ int g_off[2 * NB];

__global__ void init_off_kernel() {
    int i = threadIdx.x;
    if (i < 2 * NB) g_off[i] = 0x7FFFFFFF;
}

// Phase A: per-point lattice math -> gl0/gl1 (packed), per-batch min(gl_i - rank_i).
__global__ void phaseA_kernel(const float* __restrict__ pc) {
    const int b = blockIdx.y;
    const int n = blockIdx.x * blockDim.x + threadIdx.x;
    const float* p = pc + (size_t)b * 3 * NPTS;

    float p0 = p[n];
    float p1 = p[n + NPTS];
    float p2 = p[n + 2 * NPTS];

    // Constants exactly as numpy: float32 matrix of {2,-1}/float32(sqrt(6.0)),
    // elementwise correctly-rounded f32 division.
    const float S6 = (float)2.449489742783178;      // np.float32(np.sqrt(6.0))
    const float A  = __fdiv_rn(2.0f, S6);           //  2/sqrt6 (f32 RN)
    const float C  = __fdiv_rn(-1.0f, S6);          // -1/sqrt6 (f32 RN)

    // cuBLAS-style K-ascending FMA chain: acc = fma(E[i,k], p_k, acc), acc0 = 0.
    float e0 = __fmaf_rn(C, p2, __fmaf_rn(C, p1, __fmul_rn(A, p0)));
    float e1 = __fmaf_rn(C, p2, __fmaf_rn(A, p1, __fmul_rn(C, p0)));
    float e2 = __fmaf_rn(A, p2, __fmaf_rn(C, p1, __fmul_rn(C, p0)));

    // greedy = round(e/3)*3  (rintf = round-half-even, matches jnp.round)
    float g0 = __fmul_rn(rintf(__fdiv_rn(e0, 3.0f)), 3.0f);
    float g1 = __fmul_rn(rintf(__fdiv_rn(e1, 3.0f)), 3.0f);
    float g2 = __fmul_rn(rintf(__fdiv_rn(e2, 3.0f)), 3.0f);
    float m0 = __fadd_rn(e0, -g0);
    float m1 = __fadd_rn(e1, -g1);
    float m2 = __fadd_rn(e2, -g2);

    // rank via stable descending sort semantics (ties -> lower index first)
    int r0 = (m1 > m0) + (m2 > m0);
    int r1 = (m0 >= m1) + (m2 > m1);

    int rs = (int)__fdiv_rn(__fadd_rn(__fadd_rn(g0, g1), g2), 3.0f); // exact small int
    int gi0 = (int)g0;
    int gi1 = (int)g1;

    // sum-to-zero correction (rank stays in [0,2] after this)
    int sg = 0, c0 = 0, c1 = 0;
    if (rs > 0) { sg = -1; c0 = (r0 >= 3 - rs); c1 = (r1 >= 3 - rs); }
    else if (rs < 0) { sg = 1; c0 = (r0 < -rs); c1 = (r1 < -rs); }
    gi0 += 3 * sg * c0;
    gi1 += 3 * sg * c1;
    r0  += 3 * sg * c0 + rs;
    r1  += 3 * sg * c1 + rs;

    g_gl[b * NPTS + n] = (gi0 & 0xFFFF) | (gi1 << 16);

    // min over simplex vertices j of key component: min_j CANONICAL[r][j] = -r (r in [0,2])
    int k0 = gi0 - r0;
    int k1 = gi1 - r1;

    // warp-min then block-min, one atomicMin pair per block
    #pragma unroll
    for (int s = 16; s; s >>= 1) {
        k0 = min(k0, __shfl_xor_sync(0xFFFFFFFF, k0, s));
        k1 = min(k1, __shfl_xor_sync(0xFFFFFFFF, k1, s));
    }
    __shared__ int s0[8], s1[8];
    int wid = threadIdx.x >> 5;
    if ((threadIdx.x & 31) == 0) { s0[wid] = k0; s1[wid] = k1; }
    __syncthreads();
    if (threadIdx.x == 0) {
        int a0 = s0[0], a1 = s1[0];
        #pragma unroll
        for (int w = 1; w < 8; w++) { a0 = min(a0, s0[w]); a1 = min(a1, s1[w]); }
        atomicMin(&g_off[2 * b],     a0);
        atomicMin(&g_off[2 * b + 1], a1);
    }
}

// Phase B: scatter-add features at vertex-0 cells (bary == [1,0,0] exactly).
__global__ void phaseB_kernel(const float* __restrict__ feat,
                              float* __restrict__ out, int dual) {
    const int b = blockIdx.y;
    const int n = blockIdx.x * blockDim.x + threadIdx.x;

    int v   = g_gl[b * NPTS + n];
    int gl0 = (int)(short)(v & 0xFFFF);
    int gl1 = v >> 16;                       // arithmetic shift: sign-extends
    int off0 = g_off[2 * b];
    int off1 = g_off[2 * b + 1];

    int x0 = gl0 - off0;                     // >= 0 by construction
    int x1 = gl1 - off1;
    if (x0 < SGRID && x1 < SGRID) {          // JAX scatter drops OOB
        int pick0 = ((-off0) % 3 + 3) % 3;
        int pick1 = ((-off1) % 3 + 3) % 3;
        int r = (x0 - pick0) / 3;            // exact: x0 ≡ pick0 (mod 3)
        int c = (x1 - pick1) / 3;

        float f0 = feat[((size_t)b * 3 + 0) * NPTS + n];
        float f1 = feat[((size_t)b * 3 + 1) * NPTS + n];
        float f2 = feat[((size_t)b * 3 + 2) * NPTS + n];

        size_t base = (((size_t)b * GOUT + r) * GOUT + c) * 3;
        atomicAdd(out + base + 0, f0);
        atomicAdd(out + base + 1, f1);
        atomicAdd(out + base + 2, f2);
        if (dual) {
            atomicAdd(out + OUT_HALF + base + 0, f0);
            atomicAdd(out + OUT_HALF + base + 1, f1);
            atomicAdd(out + OUT_HALF + base + 2, f2);
        }
    }
}

extern "C" void kernel_launch(void* const* d_in, const int* in_sizes, int n_in,
                              void* d_out, int out_size) {
    const float* pc   = (const float*)d_in[0];
    const float* feat = (const float*)d_in[1];
    float* out = (float*)d_out;

    cudaMemsetAsync(d_out, 0, (size_t)out_size * sizeof(float), 0);
    init_off_kernel<<<1, 64>>>();
    phaseA_kernel<<<dim3(NPTS / 256, NB), 256>>>(pc);
    int dual = ((size_t)out_size >= 2 * OUT_HALF) ? 1 : 0;
    phaseB_kernel<<<dim3(NPTS / 256, NB), 256>>>(feat, out, dual);
}